// round 16
// baseline (speedup 1.0000x reference)
#include <cuda_runtime.h>
#include <cstdint>

// ---------------------------------------------------------------------------
// MultiScaleRoIAlign (torchvision, aligned=False, SR=2) — warp-pair + diet.
// grid=(512 rois, 4 slices of 64 ch), block=256 (4 warp-pairs), 3 blocks/SM.
// Pair p owns channels {cbase + k*4 + p}, k=0..15; cp.async8 3-buffer ring,
// prefetch 2, staged by the 64-lane pair pool with pointer-increment loops.
// One bin per lane (warp0: 0-24, warp1: 25-48); 16 precombined tap offsets
// per lane. Pair-scoped named barriers only.
// WS2=768 float2: covers ALL level-mapped windows (analytic max ~700, from
// s_scaled<28 and box sides<=~590px); direct-global fallback kept as safety.
// ---------------------------------------------------------------------------

#define WS2 768   // float2 slots per window buffer

__device__ __forceinline__ void cp_a8(uint32_t dst, const void* src)
{
    asm volatile("cp.async.ca.shared.global [%0], [%1], 8;"
                 :: "r"(dst), "l"(src) : "memory");
}
__device__ __forceinline__ void cp_a4(uint32_t dst, const void* src)
{
    asm volatile("cp.async.ca.shared.global [%0], [%1], 4;"
                 :: "r"(dst), "l"(src) : "memory");
}
#define CP_COMMIT()  asm volatile("cp.async.commit_group;" ::: "memory")
#define CP_WAIT(N)   asm volatile("cp.async.wait_group %0;" :: "n"(N) : "memory")

__global__ void __launch_bounds__(256, 3)
msroi_kernel(const float* __restrict__ f0, const float* __restrict__ f1,
             const float* __restrict__ f2, const float* __restrict__ f3,
             const float* __restrict__ boxes, float* __restrict__ out)
{
    __shared__ float2 win[4][3][WS2];                     // 72 KB
    __shared__ float s_hy[14], s_ly[14], s_hx[14], s_lx[14];
    __shared__ int   s_yl[14], s_yh[14], s_xl[14], s_xh[14];

    const int tid = threadIdx.x;
    const int n = blockIdx.x;

    float4 bx = __ldg(reinterpret_cast<const float4*>(boxes) + n);

    // LevelMapper: floor(4 + log2(sqrt(w*h)/224) + 1e-6), clip [2,5], -2
    float s = sqrtf((bx.z - bx.x) * (bx.w - bx.y));
    int lvl = (int)floorf(4.0f + log2f(s * (1.0f / 224.0f)) + 1e-6f);
    lvl = min(max(lvl, 2), 5) - 2;

    int H; float sc; const float* base;
    switch (lvl) {
        case 0:  H = 200; sc = 0.25f;    base = f0; break;
        case 1:  H = 100; sc = 0.125f;   base = f1; break;
        case 2:  H = 50;  sc = 0.0625f;  base = f2; break;
        default: H = 25;  sc = 0.03125f; base = f3; break;
    }
    const int HH = H * H;
    base += (size_t)(n >> 8) * 256 * HH;

    float x1s = bx.x * sc, y1s = bx.y * sc;
    float binw = fmaxf(bx.z * sc - x1s, 1.0f) * (1.0f / 7.0f);
    float binh = fmaxf(bx.w * sc - y1s, 1.0f) * (1.0f / 7.0f);
    float fH = (float)H;

    // window bounds
    int y0  = min((int)fmaxf(y1s + 0.25f * binh, 0.0f), H - 1);
    int x0  = min((int)fmaxf(x1s + 0.25f * binw, 0.0f), H - 1);
    int y1m = min((int)fmaxf(fminf(y1s + 6.75f * binh, fH - 1.0f), 0.0f) + 1, H - 1);
    int x1m = min((int)fmaxf(fminf(x1s + 6.75f * binw, fH - 1.0f), 0.0f) + 1, H - 1);
    const int hr  = y1m - y0 + 1;
    const int x0d = x0 & ~1;                   // float2-aligned window start
    const int wc2 = (x1m >> 1) - (x0d >> 1) + 1;
    const int rs2 = wc2 | 1;                   // odd float2 row stride
    const int rsF = rs2 * 2;                   // float row stride

    // per-sample bilinear params (14 y, 14 x), window-relative indices
    if (tid < 28) {
        bool isY = tid < 14;
        int j = isY ? tid : tid - 14;
        float o = (float)(j >> 1) + 0.25f + 0.5f * (float)(j & 1);
        float v = isY ? (y1s + o * binh) : (x1s + o * binw);
        bool valid = (v > -1.0f) && (v < fH);
        float vc = fmaxf(v, 0.0f);
        int lo = min((int)vc, H - 1);
        int hi = min(lo + 1, H - 1);
        float l = (lo >= H - 1) ? 0.0f : (vc - (float)lo);
        float h = 1.0f - l;
        if (!valid) { l = 0.0f; h = 0.0f; lo = isY ? y0 : x0d; hi = lo; }
        if (isY) { s_yl[j] = lo - y0;  s_yh[j] = hi - y0;  s_ly[j] = l; s_hy[j] = h; }
        else     { s_xl[j] = lo - x0d; s_xh[j] = hi - x0d; s_lx[j] = l; s_hx[j] = h; }
    }
    __syncthreads();                           // only block barrier

    const int warp = tid >> 5, lane = tid & 31;
    const int pair = warp >> 1, wsub = warp & 1;
    const int q = wsub * 32 + lane;            // 0..63 within pair
    const int cbase = blockIdx.y * 64;

    // one bin per lane: warp0 -> bins 0-24, warp1 -> bins 25-48
    const int binRaw = wsub ? (25 + lane) : lane;
    const bool act = lane < (25 - wsub);
    const int bin = min(binRaw, 48);

    // 16 precombined float-element tap offsets + 8 weights
    int toff[16];
    float hy0, ly0, hy1, ly1, hx0, lx0, hx1, lx1;
    {
        int oy = bin / 7, ox = bin - oy * 7;
        int j0 = oy * 2, j1 = j0 + 1, k0 = ox * 2, k1 = k0 + 1;
        int R0 = s_yl[j0] * rsF, R1 = s_yh[j0] * rsF;
        int R2 = s_yl[j1] * rsF, R3 = s_yh[j1] * rsF;
        int C0 = s_xl[k0], C1 = s_xh[k0], C2 = s_xl[k1], C3 = s_xh[k1];
        toff[0]=R0+C0;  toff[1]=R0+C1;  toff[2]=R1+C0;  toff[3]=R1+C1;
        toff[4]=R0+C2;  toff[5]=R0+C3;  toff[6]=R1+C2;  toff[7]=R1+C3;
        toff[8]=R2+C0;  toff[9]=R2+C1;  toff[10]=R3+C0; toff[11]=R3+C1;
        toff[12]=R2+C2; toff[13]=R2+C3; toff[14]=R3+C2; toff[15]=R3+C3;
        hy0=s_hy[j0]; ly0=s_ly[j0]; hy1=s_hy[j1]; ly1=s_ly[j1];
        hx0=s_hx[k0]; lx0=s_lx[k0]; hx1=s_hx[k1]; lx1=s_lx[k1];
    }

    const bool fits = (hr * rs2) <= WS2;       // uniform per block
    const bool h25 = (H == 25);
    const int H2 = H >> 1;
    const int xlim = x1m - x0d;

    // staging geometry: 64-lane pool covers wp2 x-positions x (64/wp2) rows
    const int wide = h25 ? (xlim + 1) : wc2;   // elements per row (f32 / f2)
    int wp2 = 1;
    while (wp2 < wide && wp2 < 64) wp2 <<= 1;
    const int shift = __popc(wp2 - 1);
    const int rpw = 64 >> shift;               // rows per pool step
    const int lxe = q & (wp2 - 1);
    const int lr0 = q >> shift;

    float* outn = out + (size_t)n * 12544;
    const int barid = pair + 1;

    if (fits) {
        const int gstep2 = rpw * H2;           // float2 step (!h25)
        const int sstep2 = rpw * rs2 * 8;      // smem byte step (!h25)
        const int gstepF = rpw * H;            // float step (h25)
        const int sstepF = rpw * rsF * 4;      // smem byte step (h25)

        auto stage = [&](int bf, int k) {
            const int cglob = cbase + k * 4 + pair;
            uint32_t wb = (uint32_t)__cvta_generic_to_shared(&win[pair][bf][0]);
            if (!h25) {
                const float2* g = reinterpret_cast<const float2*>(base)
                                + (size_t)cglob * (HH >> 1) + y0 * H2 + (x0d >> 1);
                if (wide <= 64) {              // common: one x-pass
                    if (lxe < wc2) {
                        const float2* gp = g + lr0 * H2 + lxe;
                        uint32_t sa = wb + (uint32_t)(lr0 * rs2 + lxe) * 8u;
                        for (int r = lr0; r < hr; r += rpw) {
                            cp_a8(sa, gp);
                            gp += gstep2; sa += (uint32_t)sstep2;
                        }
                    }
                } else {                       // rare extra-wide window
                    for (int cx0 = 0; cx0 < wc2; cx0 += wp2) {
                        int xx = cx0 + lxe;
                        if (xx >= wc2) break;
                        const float2* gp = g + lr0 * H2 + xx;
                        uint32_t sa = wb + (uint32_t)(lr0 * rs2 + xx) * 8u;
                        for (int r = lr0; r < hr; r += rpw) {
                            cp_a8(sa, gp);
                            gp += gstep2; sa += (uint32_t)sstep2;
                        }
                    }
                }
            } else {                           // H=25: wide<=25, one x-pass
                const float* g = base + (size_t)cglob * HH + y0 * H + x0d;
                if (lxe <= xlim) {
                    const float* gp = g + lr0 * H + lxe;
                    uint32_t sa = wb + (uint32_t)(lr0 * rsF + lxe) * 4u;
                    for (int r = lr0; r < hr; r += rpw) {
                        cp_a4(sa, gp);
                        gp += gstepF; sa += (uint32_t)sstepF;
                    }
                }
            }
        };

        stage(0, 0); CP_COMMIT();
        stage(1, 1); CP_COMMIT();

        #pragma unroll 1
        for (int k = 0; k < 16; k++) {
            int bf = k % 3;
            if (k + 2 < 16) {
                stage((k + 2) % 3, k + 2);     // buf freed by barrier B below
                CP_COMMIT();
                CP_WAIT(2);
            } else if (k + 1 < 16) {
                CP_WAIT(1);
            } else {
                CP_WAIT(0);
            }
            // barrier A: partner warp's copies for buf k%3 landed too
            asm volatile("bar.sync %0, 64;" :: "r"(barid) : "memory");

            const float* W = reinterpret_cast<const float*>(win[pair][bf]);
            float acc =
                  hy0 * (hx0 * W[toff[0]]  + lx0 * W[toff[1]])
                + ly0 * (hx0 * W[toff[2]]  + lx0 * W[toff[3]])
                + hy0 * (hx1 * W[toff[4]]  + lx1 * W[toff[5]])
                + ly0 * (hx1 * W[toff[6]]  + lx1 * W[toff[7]])
                + hy1 * (hx0 * W[toff[8]]  + lx0 * W[toff[9]])
                + ly1 * (hx0 * W[toff[10]] + lx0 * W[toff[11]])
                + hy1 * (hx1 * W[toff[12]] + lx1 * W[toff[13]])
                + ly1 * (hx1 * W[toff[14]] + lx1 * W[toff[15]]);
            if (act)
                outn[(cbase + k * 4 + pair) * 49 + binRaw] = acc * 0.25f;

            // barrier B: both warps done reading buf before it is restaged
            asm volatile("bar.sync %0, 64;" :: "r"(barid) : "memory");
        }
    } else {
        // ---- safety net (analytically unreachable): direct global gather ----
        #pragma unroll 1
        for (int k = 0; k < 16; k++) {
            const int cglob = cbase + k * 4 + pair;
            const float* src = base + (size_t)cglob * HH;
            int oy = bin / 7, ox = bin - oy * 7;
            float acc = 0.0f;
            #pragma unroll
            for (int sy = 0; sy < 2; sy++) {
                int j = oy * 2 + sy;
                float hy = s_hy[j], ly = s_ly[j];
                int ra = (s_yl[j] + y0) * H, rb = (s_yh[j] + y0) * H;
                #pragma unroll
                for (int sx = 0; sx < 2; sx++) {
                    int kk = ox * 2 + sx;
                    float hx = s_hx[kk], lx = s_lx[kk];
                    int xa = s_xl[kk] + x0d, xb = s_xh[kk] + x0d;
                    acc += hy * (hx * __ldg(src + ra + xa) + lx * __ldg(src + ra + xb))
                         + ly * (hx * __ldg(src + rb + xa) + lx * __ldg(src + rb + xb));
                }
            }
            if (act)
                outn[cglob * 49 + binRaw] = acc * 0.25f;
        }
    }
}

extern "C" void kernel_launch(void* const* d_in, const int* in_sizes, int n_in,
                              void* d_out, int out_size)
{
    const float* f0 = (const float*)d_in[0];
    const float* f1 = (const float*)d_in[1];
    const float* f2 = (const float*)d_in[2];
    const float* f3 = (const float*)d_in[3];
    const float* boxes = (const float*)d_in[4];
    float* out = (float*)d_out;

    msroi_kernel<<<dim3(512, 4), 256>>>(f0, f1, f2, f3, boxes, out);
}

// round 17
// speedup vs baseline: 1.3513x; 1.3513x over previous
#include <cuda_runtime.h>
#include <cstdint>

// ---------------------------------------------------------------------------
// MultiScaleRoIAlign (torchvision, aligned=False, SR=2) — warp-pair + diet,
// single-barrier pipeline. grid=(512 rois, 4 slices of 64 ch), block=256
// (4 warp-pairs), 3 blocks/SM, WS2=512 (smem 50 KB -> L1D carveout ~78 KB).
// Pair p owns channels {cbase + k*4 + p}; cp.async8 3-buffer ring.
// Per chunk: CP_WAIT(1) -> barrier A -> stage buf (k+2)%3 (safe: both warps
// finished reading it before barrier A, since compute k-1 precedes barrier A
// in program order) -> compute buf k%3 -> store. ONE barrier per chunk.
// Oversized windows (hr*rs2 > 512 float2) -> direct-global fallback.
// ---------------------------------------------------------------------------

#define WS2 512   // float2 slots per window buffer

__device__ __forceinline__ void cp_a8(uint32_t dst, const void* src)
{
    asm volatile("cp.async.ca.shared.global [%0], [%1], 8;"
                 :: "r"(dst), "l"(src) : "memory");
}
__device__ __forceinline__ void cp_a4(uint32_t dst, const void* src)
{
    asm volatile("cp.async.ca.shared.global [%0], [%1], 4;"
                 :: "r"(dst), "l"(src) : "memory");
}
#define CP_COMMIT()  asm volatile("cp.async.commit_group;" ::: "memory")
#define CP_WAIT(N)   asm volatile("cp.async.wait_group %0;" :: "n"(N) : "memory")

__global__ void __launch_bounds__(256, 3)
msroi_kernel(const float* __restrict__ f0, const float* __restrict__ f1,
             const float* __restrict__ f2, const float* __restrict__ f3,
             const float* __restrict__ boxes, float* __restrict__ out)
{
    __shared__ float2 win[4][3][WS2];                     // 48 KB
    __shared__ float s_hy[14], s_ly[14], s_hx[14], s_lx[14];
    __shared__ int   s_yl[14], s_yh[14], s_xl[14], s_xh[14];

    const int tid = threadIdx.x;
    const int n = blockIdx.x;

    float4 bx = __ldg(reinterpret_cast<const float4*>(boxes) + n);

    // LevelMapper: floor(4 + log2(sqrt(w*h)/224) + 1e-6), clip [2,5], -2
    float s = sqrtf((bx.z - bx.x) * (bx.w - bx.y));
    int lvl = (int)floorf(4.0f + log2f(s * (1.0f / 224.0f)) + 1e-6f);
    lvl = min(max(lvl, 2), 5) - 2;

    int H; float sc; const float* base;
    switch (lvl) {
        case 0:  H = 200; sc = 0.25f;    base = f0; break;
        case 1:  H = 100; sc = 0.125f;   base = f1; break;
        case 2:  H = 50;  sc = 0.0625f;  base = f2; break;
        default: H = 25;  sc = 0.03125f; base = f3; break;
    }
    const int HH = H * H;
    base += (size_t)(n >> 8) * 256 * HH;

    float x1s = bx.x * sc, y1s = bx.y * sc;
    float binw = fmaxf(bx.z * sc - x1s, 1.0f) * (1.0f / 7.0f);
    float binh = fmaxf(bx.w * sc - y1s, 1.0f) * (1.0f / 7.0f);
    float fH = (float)H;

    // window bounds
    int y0  = min((int)fmaxf(y1s + 0.25f * binh, 0.0f), H - 1);
    int x0  = min((int)fmaxf(x1s + 0.25f * binw, 0.0f), H - 1);
    int y1m = min((int)fmaxf(fminf(y1s + 6.75f * binh, fH - 1.0f), 0.0f) + 1, H - 1);
    int x1m = min((int)fmaxf(fminf(x1s + 6.75f * binw, fH - 1.0f), 0.0f) + 1, H - 1);
    const int hr  = y1m - y0 + 1;
    const int x0d = x0 & ~1;                   // float2-aligned window start
    const int wc2 = (x1m >> 1) - (x0d >> 1) + 1;
    const int rs2 = wc2 | 1;                   // odd float2 row stride
    const int rsF = rs2 * 2;                   // float row stride

    // per-sample bilinear params (14 y, 14 x), window-relative indices
    if (tid < 28) {
        bool isY = tid < 14;
        int j = isY ? tid : tid - 14;
        float o = (float)(j >> 1) + 0.25f + 0.5f * (float)(j & 1);
        float v = isY ? (y1s + o * binh) : (x1s + o * binw);
        bool valid = (v > -1.0f) && (v < fH);
        float vc = fmaxf(v, 0.0f);
        int lo = min((int)vc, H - 1);
        int hi = min(lo + 1, H - 1);
        float l = (lo >= H - 1) ? 0.0f : (vc - (float)lo);
        float h = 1.0f - l;
        if (!valid) { l = 0.0f; h = 0.0f; lo = isY ? y0 : x0d; hi = lo; }
        if (isY) { s_yl[j] = lo - y0;  s_yh[j] = hi - y0;  s_ly[j] = l; s_hy[j] = h; }
        else     { s_xl[j] = lo - x0d; s_xh[j] = hi - x0d; s_lx[j] = l; s_hx[j] = h; }
    }
    __syncthreads();                           // only block barrier

    const int warp = tid >> 5, lane = tid & 31;
    const int pair = warp >> 1, wsub = warp & 1;
    const int q = wsub * 32 + lane;            // 0..63 within pair
    const int cbase = blockIdx.y * 64;

    // one bin per lane: warp0 -> bins 0-24, warp1 -> bins 25-48
    const int binRaw = wsub ? (25 + lane) : lane;
    const bool act = lane < (25 - wsub);
    const int bin = min(binRaw, 48);

    // 16 precombined float-element tap offsets + 8 weights
    int toff[16];
    float hy0, ly0, hy1, ly1, hx0, lx0, hx1, lx1;
    {
        int oy = bin / 7, ox = bin - oy * 7;
        int j0 = oy * 2, j1 = j0 + 1, k0 = ox * 2, k1 = k0 + 1;
        int R0 = s_yl[j0] * rsF, R1 = s_yh[j0] * rsF;
        int R2 = s_yl[j1] * rsF, R3 = s_yh[j1] * rsF;
        int C0 = s_xl[k0], C1 = s_xh[k0], C2 = s_xl[k1], C3 = s_xh[k1];
        toff[0]=R0+C0;  toff[1]=R0+C1;  toff[2]=R1+C0;  toff[3]=R1+C1;
        toff[4]=R0+C2;  toff[5]=R0+C3;  toff[6]=R1+C2;  toff[7]=R1+C3;
        toff[8]=R2+C0;  toff[9]=R2+C1;  toff[10]=R3+C0; toff[11]=R3+C1;
        toff[12]=R2+C2; toff[13]=R2+C3; toff[14]=R3+C2; toff[15]=R3+C3;
        hy0=s_hy[j0]; ly0=s_ly[j0]; hy1=s_hy[j1]; ly1=s_ly[j1];
        hx0=s_hx[k0]; lx0=s_lx[k0]; hx1=s_hx[k1]; lx1=s_lx[k1];
    }

    const bool fits = (hr * rs2) <= WS2;       // uniform per block
    const bool h25 = (H == 25);
    const int H2 = H >> 1;
    const int xlim = x1m - x0d;

    // staging geometry: 64-lane pool covers wp2 x-positions x (64/wp2) rows
    const int wide = h25 ? (xlim + 1) : wc2;   // elements per row (f32 / f2)
    int wp2 = 1;
    while (wp2 < wide && wp2 < 64) wp2 <<= 1;
    const int shift = __popc(wp2 - 1);
    const int rpw = 64 >> shift;               // rows per pool step
    const int lxe = q & (wp2 - 1);
    const int lr0 = q >> shift;

    float* outn = out + (size_t)n * 12544;
    const int barid = pair + 1;

    if (fits) {
        const int gstep2 = rpw * H2;           // float2 step (!h25)
        const int sstep2 = rpw * rs2 * 8;      // smem byte step (!h25)
        const int gstepF = rpw * H;            // float step (h25)
        const int sstepF = rpw * rsF * 4;      // smem byte step (h25)

        auto stage = [&](int bf, int k) {
            const int cglob = cbase + k * 4 + pair;
            uint32_t wb = (uint32_t)__cvta_generic_to_shared(&win[pair][bf][0]);
            if (!h25) {
                const float2* g = reinterpret_cast<const float2*>(base)
                                + (size_t)cglob * (HH >> 1) + y0 * H2 + (x0d >> 1);
                if (wide <= 64) {              // common: one x-pass
                    if (lxe < wc2) {
                        const float2* gp = g + lr0 * H2 + lxe;
                        uint32_t sa = wb + (uint32_t)(lr0 * rs2 + lxe) * 8u;
                        for (int r = lr0; r < hr; r += rpw) {
                            cp_a8(sa, gp);
                            gp += gstep2; sa += (uint32_t)sstep2;
                        }
                    }
                } else {                       // rare extra-wide window
                    for (int cx0 = 0; cx0 < wc2; cx0 += wp2) {
                        int xx = cx0 + lxe;
                        if (xx >= wc2) break;
                        const float2* gp = g + lr0 * H2 + xx;
                        uint32_t sa = wb + (uint32_t)(lr0 * rs2 + xx) * 8u;
                        for (int r = lr0; r < hr; r += rpw) {
                            cp_a8(sa, gp);
                            gp += gstep2; sa += (uint32_t)sstep2;
                        }
                    }
                }
            } else {                           // H=25: wide<=25, one x-pass
                const float* g = base + (size_t)cglob * HH + y0 * H + x0d;
                if (lxe <= xlim) {
                    const float* gp = g + lr0 * H + lxe;
                    uint32_t sa = wb + (uint32_t)(lr0 * rsF + lxe) * 4u;
                    for (int r = lr0; r < hr; r += rpw) {
                        cp_a4(sa, gp);
                        gp += gstepF; sa += (uint32_t)sstepF;
                    }
                }
            }
        };

        stage(0, 0); CP_COMMIT();
        stage(1, 1); CP_COMMIT();

        #pragma unroll 1
        for (int k = 0; k < 16; k++) {
            int bf = k % 3;
            // pending groups here: {k, k+1} (k<15) -> WAIT(1) lands group k;
            // at k==15 only {15} remains -> WAIT(0).
            if (k < 15) { CP_WAIT(1); } else { CP_WAIT(0); }

            // barrier A: partner's copies for buf k%3 landed, AND both warps
            // have finished reading buf (k-1)%3 (compute k-1 precedes this
            // barrier in program order) -> staging it below is safe.
            asm volatile("bar.sync %0, 64;" :: "r"(barid) : "memory");

            if (k + 2 < 16) {
                stage((k + 2) % 3, k + 2);     // writes buf (k-1)%3
                CP_COMMIT();
            }

            const float* W = reinterpret_cast<const float*>(win[pair][bf]);
            float acc =
                  hy0 * (hx0 * W[toff[0]]  + lx0 * W[toff[1]])
                + ly0 * (hx0 * W[toff[2]]  + lx0 * W[toff[3]])
                + hy0 * (hx1 * W[toff[4]]  + lx1 * W[toff[5]])
                + ly0 * (hx1 * W[toff[6]]  + lx1 * W[toff[7]])
                + hy1 * (hx0 * W[toff[8]]  + lx0 * W[toff[9]])
                + ly1 * (hx0 * W[toff[10]] + lx0 * W[toff[11]])
                + hy1 * (hx1 * W[toff[12]] + lx1 * W[toff[13]])
                + ly1 * (hx1 * W[toff[14]] + lx1 * W[toff[15]]);
            if (act)
                outn[(cbase + k * 4 + pair) * 49 + binRaw] = acc * 0.25f;
        }
    } else {
        // ---- rare oversized window: direct global gather ----
        #pragma unroll 1
        for (int k = 0; k < 16; k++) {
            const int cglob = cbase + k * 4 + pair;
            const float* src = base + (size_t)cglob * HH;
            int oy = bin / 7, ox = bin - oy * 7;
            float acc = 0.0f;
            #pragma unroll
            for (int sy = 0; sy < 2; sy++) {
                int j = oy * 2 + sy;
                float hy = s_hy[j], ly = s_ly[j];
                int ra = (s_yl[j] + y0) * H, rb = (s_yh[j] + y0) * H;
                #pragma unroll
                for (int sx = 0; sx < 2; sx++) {
                    int kk = ox * 2 + sx;
                    float hx = s_hx[kk], lx = s_lx[kk];
                    int xa = s_xl[kk] + x0d, xb = s_xh[kk] + x0d;
                    acc += hy * (hx * __ldg(src + ra + xa) + lx * __ldg(src + ra + xb))
                         + ly * (hx * __ldg(src + rb + xa) + lx * __ldg(src + rb + xb));
                }
            }
            if (act)
                outn[cglob * 49 + binRaw] = acc * 0.25f;
        }
    }
}

extern "C" void kernel_launch(void* const* d_in, const int* in_sizes, int n_in,
                              void* d_out, int out_size)
{
    const float* f0 = (const float*)d_in[0];
    const float* f1 = (const float*)d_in[1];
    const float* f2 = (const float*)d_in[2];
    const float* f3 = (const float*)d_in[3];
    const float* boxes = (const float*)d_in[4];
    float* out = (float*)d_out;

    msroi_kernel<<<dim3(512, 4), 256>>>(f0, f1, f2, f3, boxes, out);
}